// round 4
// baseline (speedup 1.0000x reference)
#include <cuda_runtime.h>
#include <cstdint>

// Problem constants
#define BNUM   1024
#define QNUM   96
#define CNUM   16
#define HNUM   100
#define NSTEPS_K 100
#define QP1    97            // Q+1 state features per row
#define ROWS   (BNUM*CNUM)   // 16384 independent rows
#define MT     112           // rows per CTA (147 CTAs, last ragged)
#define GRID   ((ROWS + MT - 1) / MT)   // 147
#define NTHREADS 448         // 28 ty x 16 tx
#define RM     4             // rows per thread (2 float2 pairs)
#define RN     7             // output cols per thread (16*7=112 >= 100)

typedef unsigned int       u32t;
typedef unsigned long long u64t;

// Activation layout: col-major, stride 128, row-rotated by (col&7)*4.
//   elem(col,row) at  col*128 + ((row + ((col&7)<<2)) & 127)
#define ASTR 128

// Shared memory layout (float offsets)
#define OFF_XS   0
#define SZ_XS    (QP1*ASTR)            // 12416
#define OFF_HS   (OFF_XS + SZ_XS)      // 12416
#define SZ_HS    (HNUM*ASTR)           // 12800
#define OFF_W1   (OFF_HS + SZ_HS)      // 25216
#define SZ_W1    (QP1*HNUM)            // 9700  K-major [k][j]
#define OFF_W1T  (OFF_W1 + SZ_W1)      // t column of W1 (100)
#define OFF_W2   (OFF_W1T + HNUM)
#define SZ_W2    (HNUM*HNUM)           // 10000
#define OFF_W3   (OFF_W2 + SZ_W2)
#define SZ_W3    (HNUM*QP1)            // 9700
#define OFF_B1   (OFF_W3 + SZ_W3)
#define OFF_B2   (OFF_B1 + HNUM)
#define OFF_B3   (OFF_B2 + HNUM)
#define SMEM_FLOATS (OFF_B3 + QP1)     // 55013 floats
#define SMEM_BYTES  (SMEM_FLOATS * 4)  // 220052 B

extern __shared__ float smem[];

__device__ __forceinline__ void fma2(u64t& d, u64t a, u64t b) {
    asm("fma.rn.f32x2 %0, %1, %2, %0;" : "+l"(d) : "l"(a), "l"(b));
}
__device__ __forceinline__ u64t dup2(float w) {
    u64t r;
    asm("mov.b64 %0, {%1, %1};" : "=l"(r) : "f"(w));
    return r;
}
__device__ __forceinline__ void unpack2(u64t v, float& lo, float& hi) {
    asm("mov.b64 {%0, %1}, %2;" : "=f"(lo), "=f"(hi) : "l"(v));
}
__device__ __forceinline__ float tanh_fast(float x) {
    asm("tanh.approx.f32 %0, %0;" : "+f"(x));
    return x;
}
__device__ __forceinline__ void lds_v2u64(u32t addr, u64t& a, u64t& b) {
    asm("ld.shared.v2.b64 {%0, %1}, [%2];" : "=l"(a), "=l"(b) : "r"(addr));
}
__device__ __forceinline__ void sts_v2f32(u32t addr, float lo, float hi) {
    asm volatile("st.shared.v2.f32 [%0], {%1, %2};" :: "r"(addr), "f"(lo), "f"(hi));
}

__device__ __forceinline__ int aoff(int col, int row) {
    return col * ASTR + ((row + ((col & 7) << 2)) & 127);
}

// K-loop GEMM micro-kernel: acc[2][RN] (row-pairs x cols) += A[k][rows] * W[k][col]
template<int KTOT, int WS>
__device__ __forceinline__ void gemm_tile(u32t a_u32, const float* __restrict__ Wp,
                                          const int (&col)[RN],
                                          const int (&g0a)[8],
                                          u64t (&acc)[2][RN])
{
    int k = 0;
    u32t xaddr = a_u32;
    #pragma unroll 1
    for (; k + 8 <= KTOT; k += 8, xaddr += 8 * ASTR * 4, Wp += 8 * WS) {
        #pragma unroll
        for (int u = 0; u < 8; u++) {
            u64t a0, a1;
            lds_v2u64(xaddr + g0a[u], a0, a1);
            #pragma unroll
            for (int i = 0; i < RN; i++) {
                u64t b2 = dup2(Wp[u * WS + col[i]]);
                fma2(acc[0][i], a0, b2);
                fma2(acc[1][i], a1, b2);
            }
        }
    }
    constexpr int REM = KTOT & 7;
    #pragma unroll
    for (int u = 0; u < REM; u++) {
        u64t a0, a1;
        lds_v2u64(xaddr + g0a[u], a0, a1);
        #pragma unroll
        for (int i = 0; i < RN; i++) {
            u64t b2 = dup2(Wp[u * WS + col[i]]);
            fma2(acc[0][i], a0, b2);
            fma2(acc[1][i], a1, b2);
        }
    }
}

__global__ __launch_bounds__(NTHREADS, 1)
void arima_flow_kernel(const float* __restrict__ series,
                       const float* __restrict__ rand_error,
                       const float* __restrict__ W1, const float* __restrict__ b1,
                       const float* __restrict__ W2, const float* __restrict__ b2,
                       const float* __restrict__ W3, const float* __restrict__ b3,
                       float* __restrict__ out)
{
    float* Xs  = smem + OFF_XS;
    float* W1s = smem + OFF_W1;
    float* W1t = smem + OFF_W1T;
    float* W2s = smem + OFF_W2;
    float* W3s = smem + OFF_W3;
    float* B1s = smem + OFF_B1;
    float* B2s = smem + OFF_B2;
    float* B3s = smem + OFF_B3;

    u32t sb;
    asm("{ .reg .u64 t; cvta.to.shared.u64 t, %1; cvt.u32.u64 %0, t; }"
        : "=r"(sb) : "l"(smem));
    const u32t XS_U = sb + OFF_XS * 4;
    const u32t HS_U = sb + OFF_HS * 4;

    const int tid  = threadIdx.x;
    const int tx   = tid & 15;
    const int ty   = tid >> 4;      // 0..27
    const int row0 = ty * RM;       // 0..108
    const int base = blockIdx.x * MT;

    // ---- load weights (transpose to K-major) ----
    for (int idx = tid; idx < HNUM * QP1; idx += NTHREADS) {
        int j = idx / QP1, k = idx - j * QP1;
        W1s[k * HNUM + j] = W1[j * (QNUM + 2) + k];
    }
    for (int j = tid; j < HNUM; j += NTHREADS) {
        W1t[j] = W1[j * (QNUM + 2) + (QNUM + 1)];
        B1s[j] = b1[j];
        B2s[j] = b2[j];
    }
    for (int idx = tid; idx < HNUM * HNUM; idx += NTHREADS) {
        int j = idx / HNUM, k = idx - j * HNUM;
        W2s[k * HNUM + j] = W2[idx];
    }
    for (int idx = tid; idx < QP1 * HNUM; idx += NTHREADS) {
        int j = idx / HNUM, k = idx - j * HNUM;
        W3s[k * QP1 + j] = W3[idx];
    }
    for (int j = tid; j < QP1; j += NTHREADS) B3s[j] = b3[j];

    // ---- x0 = cat(series, rand_error) into swizzled Xs (guard ragged tail) ----
    for (int idx = tid; idx < QP1 * MT; idx += NTHREADS) {
        int q = idx / MT, m = idx - q * MT;
        int row = base + m;
        float v = 0.0f;
        if (row < ROWS) {
            int b = row >> 4, c = row & 15;
            v = (q < QNUM) ? series[(b * QNUM + q) * CNUM + c]
                           : rand_error[b * CNUM + c];
        }
        Xs[aoff(q, m)] = v;
    }
    __syncthreads();

    // ---- per-thread constants ----
    int colh[RN], colq[RN];
    bool vh[RN], vq[RN];
    #pragma unroll
    for (int i = 0; i < RN; i++) {
        int j = i * 16 + tx;
        vh[i] = (j < HNUM); colh[i] = vh[i] ? j : 0;
        vq[i] = (j < QP1);  colq[i] = vq[i] ? j : 0;
    }
    // swizzle table: byte offset of this thread's 4-row group for each (k&7)
    int g0a[8];
    #pragma unroll
    for (int u = 0; u < 8; u++)
        g0a[u] = ((row0 + 4 * u) & 127) * 4 + u * ASTR * 4;
    // store-side: this thread's cols all have col&7 == tx&7
    const int swzc = (tx & 7) << 2;
    int rowoff[2];
    #pragma unroll
    for (int r2 = 0; r2 < 2; r2++)
        rowoff[r2] = ((row0 + 2 * r2 + swzc) & 127) * 4;

    // noise snapshot
    float noise[RM][RN];
    #pragma unroll
    for (int i = 0; i < RN; i++)
        #pragma unroll
        for (int r = 0; r < RM; r++)
            noise[r][i] = Xs[aoff(colq[i], row0 + r)];

    const float dt = 1.0f / (float)NSTEPS_K;
    u64t acc[2][RN];

    for (int s = 0; s < NSTEPS_K; s++) {
        const float t = (float)s / (float)NSTEPS_K;
        __syncthreads();  // [A] Xs stable, Hs free

        // ===== Layer 1: h1 = tanh(X @ W1^T + b1 + t*W1t) =====
        #pragma unroll
        for (int i = 0; i < RN; i++) {
            float bt = fmaf(t, W1t[colh[i]], B1s[colh[i]]);
            u64t b2 = dup2(bt);
            acc[0][i] = b2; acc[1][i] = b2;
        }
        gemm_tile<QP1, HNUM>(XS_U, W1s, colh, g0a, acc);
        #pragma unroll
        for (int i = 0; i < RN; i++) {
            if (vh[i]) {
                u32t cbase = HS_U + colh[i] * (ASTR * 4);
                #pragma unroll
                for (int r2 = 0; r2 < 2; r2++) {
                    float lo, hi; unpack2(acc[r2][i], lo, hi);
                    sts_v2f32(cbase + rowoff[r2], tanh_fast(lo), tanh_fast(hi));
                }
            }
        }
        __syncthreads();  // [B] h1 visible

        // ===== Layer 2: h2 = tanh(h1 @ W2^T + b2) =====
        #pragma unroll
        for (int i = 0; i < RN; i++) {
            u64t b2 = dup2(B2s[colh[i]]);
            acc[0][i] = b2; acc[1][i] = b2;
        }
        gemm_tile<HNUM, HNUM>(HS_U, W2s, colh, g0a, acc);
        float h2lo[2][RN], h2hi[2][RN];
        #pragma unroll
        for (int i = 0; i < RN; i++)
            #pragma unroll
            for (int r2 = 0; r2 < 2; r2++) {
                float lo, hi; unpack2(acc[r2][i], lo, hi);
                h2lo[r2][i] = tanh_fast(lo);
                h2hi[r2][i] = tanh_fast(hi);
            }
        __syncthreads();  // [C] all h1 readers done
        #pragma unroll
        for (int i = 0; i < RN; i++) {
            if (vh[i]) {
                u32t cbase = HS_U + colh[i] * (ASTR * 4);
                #pragma unroll
                for (int r2 = 0; r2 < 2; r2++)
                    sts_v2f32(cbase + rowoff[r2], h2lo[r2][i], h2hi[r2][i]);
            }
        }
        __syncthreads();  // [D] h2 visible

        // ===== Layer 3 + Euler: x += (h2 @ W3^T + b3 - noise) * dt =====
        #pragma unroll
        for (int i = 0; i < RN; i++) {
            u64t b2 = dup2(B3s[colq[i]]);
            acc[0][i] = b2; acc[1][i] = b2;
        }
        gemm_tile<HNUM, QP1>(HS_U, W3s, colq, g0a, acc);
        #pragma unroll
        for (int i = 0; i < RN; i++) {
            if (vq[i]) {
                u32t cbase = XS_U + colq[i] * (ASTR * 4);
                #pragma unroll
                for (int r2 = 0; r2 < 2; r2++) {
                    u32t addr = cbase + rowoff[r2];
                    float plo, phi; unpack2(acc[r2][i], plo, phi);
                    float xlo, xhi;
                    asm("ld.shared.v2.f32 {%0, %1}, [%2];"
                        : "=f"(xlo), "=f"(xhi) : "r"(addr));
                    xlo = fmaf(plo - noise[2 * r2][i],     dt, xlo);
                    xhi = fmaf(phi - noise[2 * r2 + 1][i], dt, xhi);
                    sts_v2f32(addr, xlo, xhi);
                }
            }
        }
        // next iteration's [A] protects Xs
    }

    __syncthreads();
    // ---- write result (B, 97, C), guard ragged tail ----
    for (int idx = tid; idx < QP1 * MT; idx += NTHREADS) {
        int q = idx / MT, m = idx - q * MT;
        int row = base + m;
        if (row < ROWS) {
            int b = row >> 4, c = row & 15;
            out[(b * QP1 + q) * CNUM + c] = Xs[aoff(q, m)];
        }
    }
}

extern "C" void kernel_launch(void* const* d_in, const int* in_sizes, int n_in,
                              void* d_out, int out_size)
{
    const float* series     = (const float*)d_in[0];
    const float* rand_error = (const float*)d_in[1];
    const float* W1 = (const float*)d_in[2];
    const float* b1 = (const float*)d_in[3];
    const float* W2 = (const float*)d_in[4];
    const float* b2 = (const float*)d_in[5];
    const float* W3 = (const float*)d_in[6];
    const float* b3 = (const float*)d_in[7];
    float* out = (float*)d_out;

    cudaFuncSetAttribute(arima_flow_kernel,
                         cudaFuncAttributeMaxDynamicSharedMemorySize, SMEM_BYTES);
    arima_flow_kernel<<<GRID, NTHREADS, SMEM_BYTES>>>(
        series, rand_error, W1, b1, W2, b2, W3, b3, out);
}

// round 5
// speedup vs baseline: 1.1175x; 1.1175x over previous
#include <cuda_runtime.h>
#include <cstdint>

// Problem constants
#define BNUM   1024
#define QNUM   96
#define CNUM   16
#define HNUM   100
#define NSTEPS_K 100
#define QP1    97            // Q+1 state features per row
#define ROWS   (BNUM*CNUM)   // 16384 independent rows
#define MT     128           // rows per CTA
#define NTHREADS 256         // 16x16
#define RM     8             // rows per thread (4 float2 pairs)
#define RN     7             // output cols per thread (16*7=112 >= 100)

typedef unsigned int       u32t;
typedef unsigned long long u64t;

// Activation layout: col-major, stride 128, row-rotated by (col&7)*4.
//   elem(col,row) at  col*128 + ((row + ((col&7)<<2)) & 127)
#define ASTR 128
// Weight layout: j-major rows padded to stride 108 floats (16B-unit stride 27,
// odd -> conflict-capped float4 loads)
#define WSTR 108

// Shared memory layout (float offsets)
#define OFF_XS   0
#define SZ_XS    (QP1*ASTR)            // 12416
#define OFF_HS   (OFF_XS + SZ_XS)      // 12416
#define SZ_HS    (HNUM*ASTR)           // 12800
#define OFF_W1   (OFF_HS + SZ_HS)      // 25216
#define SZ_W1    (HNUM*WSTR)           // 10800  j-major [j][k], k<97
#define OFF_W1T  (OFF_W1 + SZ_W1)      // t column of W1 (100)
#define OFF_W2   (OFF_W1T + HNUM)
#define SZ_W2    (HNUM*WSTR)           // 10800  [j][k], k<100
#define OFF_W3   (OFF_W2 + SZ_W2)
#define SZ_W3    (QP1*WSTR)            // 10476  [j][k], j<97, k<100
#define OFF_B1   (OFF_W3 + SZ_W3)
#define OFF_B2   (OFF_B1 + HNUM)
#define OFF_B3   (OFF_B2 + HNUM)
#define SMEM_FLOATS (OFF_B3 + QP1)     // 57689 floats
#define SMEM_BYTES  (SMEM_FLOATS * 4)  // 230756 B (fits 227KB opt-in = 232448)

extern __shared__ float smem[];

__device__ __forceinline__ void fma2(u64t& d, u64t a, u64t b) {
    asm("fma.rn.f32x2 %0, %1, %2, %0;" : "+l"(d) : "l"(a), "l"(b));
}
__device__ __forceinline__ u64t dup2(float w) {
    u64t r;
    asm("mov.b64 %0, {%1, %1};" : "=l"(r) : "f"(w));
    return r;
}
__device__ __forceinline__ void unpack2(u64t v, float& lo, float& hi) {
    asm("mov.b64 {%0, %1}, %2;" : "=f"(lo), "=f"(hi) : "l"(v));
}
__device__ __forceinline__ float tanh_fast(float x) {
    asm("tanh.approx.f32 %0, %0;" : "+f"(x));
    return x;
}
__device__ __forceinline__ void lds_v2u64(u32t addr, u64t& a, u64t& b) {
    asm("ld.shared.v2.b64 {%0, %1}, [%2];" : "=l"(a), "=l"(b) : "r"(addr));
}
__device__ __forceinline__ void lds_v4f32(u32t addr, float& a, float& b, float& c, float& d) {
    asm("ld.shared.v4.f32 {%0, %1, %2, %3}, [%4];"
        : "=f"(a), "=f"(b), "=f"(c), "=f"(d) : "r"(addr));
}
__device__ __forceinline__ void sts_v2f32(u32t addr, float lo, float hi) {
    asm volatile("st.shared.v2.f32 [%0], {%1, %2};" :: "r"(addr), "f"(lo), "f"(hi));
}

__device__ __forceinline__ int aoff(int col, int row) {
    return col * ASTR + ((row + ((col & 7) << 2)) & 127);
}

// 4-k micro-step: weights w0..w3 (per col), activations via tables at g..g+3
__device__ __forceinline__ void step4(u32t xaddr, int gbase,
                                      const int (&g0a)[8], const int (&g1a)[8],
                                      const float (&w0)[RN], const float (&w1)[RN],
                                      const float (&w2)[RN], const float (&w3)[RN],
                                      u64t (&acc)[4][RN])
{
    #pragma unroll
    for (int u = 0; u < 4; u++) {
        u64t a0, a1, a2, a3;
        lds_v2u64(xaddr + g0a[gbase + u], a0, a1);
        lds_v2u64(xaddr + g1a[gbase + u], a2, a3);
        #pragma unroll
        for (int i = 0; i < RN; i++) {
            float wv = (u == 0) ? w0[i] : (u == 1) ? w1[i] : (u == 2) ? w2[i] : w3[i];
            u64t b2 = dup2(wv);
            fma2(acc[0][i], a0, b2);
            fma2(acc[1][i], a1, b2);
            fma2(acc[2][i], a2, b2);
            fma2(acc[3][i], a3, b2);
        }
    }
}

// GEMM tile: acc += A[k][rows] * W[col][k], W j-major float4 loads
template<int KTOT>
__device__ __forceinline__ void gemm_tile(u32t a_u32, u32t w_u32,
                                          const u32t (&wof)[RN],
                                          const int (&g0a)[8], const int (&g1a)[8],
                                          u64t (&acc)[4][RN])
{
    u32t xaddr = a_u32;
    int k = 0;
    #pragma unroll 1
    for (; k + 8 <= KTOT; k += 8, xaddr += 8 * ASTR * 4) {
        float w0[RN], w1[RN], w2[RN], w3[RN];
        #pragma unroll
        for (int i = 0; i < RN; i++)
            lds_v4f32(w_u32 + wof[i] + k * 4, w0[i], w1[i], w2[i], w3[i]);
        step4(xaddr, 0, g0a, g1a, w0, w1, w2, w3, acc);
        #pragma unroll
        for (int i = 0; i < RN; i++)
            lds_v4f32(w_u32 + wof[i] + (k + 4) * 4, w0[i], w1[i], w2[i], w3[i]);
        step4(xaddr, 4, g0a, g1a, w0, w1, w2, w3, acc);
    }
    if (KTOT & 4) {
        float w0[RN], w1[RN], w2[RN], w3[RN];
        #pragma unroll
        for (int i = 0; i < RN; i++)
            lds_v4f32(w_u32 + wof[i] + k * 4, w0[i], w1[i], w2[i], w3[i]);
        step4(xaddr, 0, g0a, g1a, w0, w1, w2, w3, acc);
        k += 4;
    }
    // scalar remainder (only KTOT=97 -> 1 iter, at g = (KTOT&4?4:0))
    #pragma unroll
    for (int r = 0; r < (KTOT & 3); r++) {
        int g = ((KTOT & 4) ? 4 : 0) + r;
        u64t a0, a1, a2, a3;
        lds_v2u64(xaddr + g0a[g], a0, a1);
        lds_v2u64(xaddr + g1a[g], a2, a3);
        #pragma unroll
        for (int i = 0; i < RN; i++) {
            float wv = smem[0];  // placeholder, replaced below
            (void)wv;
            float ws;
            asm("ld.shared.f32 %0, [%1];" : "=f"(ws) : "r"(w_u32 + wof[i] + (k + r) * 4));
            u64t b2 = dup2(ws);
            fma2(acc[0][i], a0, b2);
            fma2(acc[1][i], a1, b2);
            fma2(acc[2][i], a2, b2);
            fma2(acc[3][i], a3, b2);
        }
    }
}

__global__ __launch_bounds__(NTHREADS, 1)
void arima_flow_kernel(const float* __restrict__ series,
                       const float* __restrict__ rand_error,
                       const float* __restrict__ W1, const float* __restrict__ b1,
                       const float* __restrict__ W2, const float* __restrict__ b2,
                       const float* __restrict__ W3, const float* __restrict__ b3,
                       float* __restrict__ out)
{
    float* Xs  = smem + OFF_XS;
    float* W1s = smem + OFF_W1;
    float* W1t = smem + OFF_W1T;
    float* W2s = smem + OFF_W2;
    float* W3s = smem + OFF_W3;
    float* B1s = smem + OFF_B1;
    float* B2s = smem + OFF_B2;
    float* B3s = smem + OFF_B3;

    u32t sb;
    asm("{ .reg .u64 t; cvta.to.shared.u64 t, %1; cvt.u32.u64 %0, t; }"
        : "=r"(sb) : "l"(smem));
    const u32t XS_U  = sb + OFF_XS * 4;
    const u32t HS_U  = sb + OFF_HS * 4;
    const u32t W1_U  = sb + OFF_W1 * 4;
    const u32t W2_U  = sb + OFF_W2 * 4;
    const u32t W3_U  = sb + OFF_W3 * 4;

    const int tid  = threadIdx.x;
    const int tx   = tid & 15;
    const int ty   = tid >> 4;
    const int row0 = ty * RM;
    const int base = blockIdx.x * MT;

    // ---- load weights, j-major (natural layout), padded stride WSTR ----
    for (int idx = tid; idx < HNUM * QP1; idx += NTHREADS) {
        int j = idx / QP1, k = idx - j * QP1;
        W1s[j * WSTR + k] = W1[j * (QNUM + 2) + k];
    }
    for (int j = tid; j < HNUM; j += NTHREADS) {
        W1t[j] = W1[j * (QNUM + 2) + (QNUM + 1)];
        B1s[j] = b1[j];
        B2s[j] = b2[j];
    }
    for (int idx = tid; idx < HNUM * HNUM; idx += NTHREADS) {
        int j = idx / HNUM, k = idx - j * HNUM;
        W2s[j * WSTR + k] = W2[idx];
    }
    for (int idx = tid; idx < QP1 * HNUM; idx += NTHREADS) {
        int j = idx / HNUM, k = idx - j * HNUM;
        W3s[j * WSTR + k] = W3[idx];
    }
    for (int j = tid; j < QP1; j += NTHREADS) B3s[j] = b3[j];

    // ---- x0 = cat(series, rand_error) into swizzled Xs ----
    for (int idx = tid; idx < QP1 * MT; idx += NTHREADS) {
        int q = idx / MT, m = idx - q * MT;
        int row = base + m;
        int b = row >> 4, c = row & 15;
        float v = (q < QNUM) ? series[(b * QNUM + q) * CNUM + c]
                             : rand_error[b * CNUM + c];
        Xs[aoff(q, m)] = v;
    }
    __syncthreads();

    // ---- per-thread constants ----
    int colh[RN], colq[RN];
    bool vh[RN], vq[RN];
    u32t wofh[RN], wofq[RN];
    #pragma unroll
    for (int i = 0; i < RN; i++) {
        int j = i * 16 + tx;
        vh[i] = (j < HNUM); colh[i] = vh[i] ? j : 0;
        vq[i] = (j < QP1);  colq[i] = vq[i] ? j : 0;
        wofh[i] = (u32t)colh[i] * (WSTR * 4);
        wofq[i] = (u32t)colq[i] * (WSTR * 4);
    }
    // activation swizzle tables: byte offsets of the two 4-row groups per (k&7)
    int g0a[8], g1a[8];
    #pragma unroll
    for (int u = 0; u < 8; u++) {
        g0a[u] = ((row0     + 4 * u) & 127) * 4 + u * ASTR * 4;
        g1a[u] = ((row0 + 4 + 4 * u) & 127) * 4 + u * ASTR * 4;
    }
    // store-side: this thread's cols all share col&7 == tx&7
    const int swzc = (tx & 7) << 2;
    int rowoff[4];
    #pragma unroll
    for (int r2 = 0; r2 < 4; r2++)
        rowoff[r2] = ((row0 + 2 * r2 + swzc) & 127) * 4;

    // noise snapshot
    float noise[RM][RN];
    #pragma unroll
    for (int i = 0; i < RN; i++)
        #pragma unroll
        for (int r = 0; r < RM; r++)
            noise[r][i] = Xs[aoff(colq[i], row0 + r)];

    const float dt = 1.0f / (float)NSTEPS_K;
    u64t acc[4][RN];

    for (int s = 0; s < NSTEPS_K; s++) {
        const float t = (float)s / (float)NSTEPS_K;
        __syncthreads();  // [A] Xs stable, Hs free

        // ===== Layer 1: h1 = tanh(X @ W1^T + b1 + t*W1t) =====
        #pragma unroll
        for (int i = 0; i < RN; i++) {
            float bt = fmaf(t, W1t[colh[i]], B1s[colh[i]]);
            u64t b2 = dup2(bt);
            #pragma unroll
            for (int r2 = 0; r2 < 4; r2++) acc[r2][i] = b2;
        }
        gemm_tile<QP1>(XS_U, W1_U, wofh, g0a, g1a, acc);
        #pragma unroll
        for (int i = 0; i < RN; i++) {
            if (vh[i]) {
                u32t cbase = HS_U + colh[i] * (ASTR * 4);
                #pragma unroll
                for (int r2 = 0; r2 < 4; r2++) {
                    float lo, hi; unpack2(acc[r2][i], lo, hi);
                    sts_v2f32(cbase + rowoff[r2], tanh_fast(lo), tanh_fast(hi));
                }
            }
        }
        __syncthreads();  // [B] h1 visible

        // ===== Layer 2: h2 = tanh(h1 @ W2^T + b2) =====
        #pragma unroll
        for (int i = 0; i < RN; i++) {
            u64t b2 = dup2(B2s[colh[i]]);
            #pragma unroll
            for (int r2 = 0; r2 < 4; r2++) acc[r2][i] = b2;
        }
        gemm_tile<HNUM>(HS_U, W2_U, wofh, g0a, g1a, acc);
        float h2lo[4][RN], h2hi[4][RN];
        #pragma unroll
        for (int i = 0; i < RN; i++)
            #pragma unroll
            for (int r2 = 0; r2 < 4; r2++) {
                float lo, hi; unpack2(acc[r2][i], lo, hi);
                h2lo[r2][i] = tanh_fast(lo);
                h2hi[r2][i] = tanh_fast(hi);
            }
        __syncthreads();  // [C] all h1 readers done
        #pragma unroll
        for (int i = 0; i < RN; i++) {
            if (vh[i]) {
                u32t cbase = HS_U + colh[i] * (ASTR * 4);
                #pragma unroll
                for (int r2 = 0; r2 < 4; r2++)
                    sts_v2f32(cbase + rowoff[r2], h2lo[r2][i], h2hi[r2][i]);
            }
        }
        __syncthreads();  // [D] h2 visible

        // ===== Layer 3 + Euler: x += (h2 @ W3^T + b3 - noise) * dt =====
        #pragma unroll
        for (int i = 0; i < RN; i++) {
            u64t b2 = dup2(B3s[colq[i]]);
            #pragma unroll
            for (int r2 = 0; r2 < 4; r2++) acc[r2][i] = b2;
        }
        gemm_tile<HNUM>(HS_U, W3_U, wofq, g0a, g1a, acc);
        #pragma unroll
        for (int i = 0; i < RN; i++) {
            if (vq[i]) {
                u32t cbase = XS_U + colq[i] * (ASTR * 4);
                #pragma unroll
                for (int r2 = 0; r2 < 4; r2++) {
                    u32t addr = cbase + rowoff[r2];
                    float plo, phi; unpack2(acc[r2][i], plo, phi);
                    float xlo, xhi;
                    asm("ld.shared.v2.f32 {%0, %1}, [%2];"
                        : "=f"(xlo), "=f"(xhi) : "r"(addr));
                    xlo = fmaf(plo - noise[2 * r2][i],     dt, xlo);
                    xhi = fmaf(phi - noise[2 * r2 + 1][i], dt, xhi);
                    sts_v2f32(addr, xlo, xhi);
                }
            }
        }
        // next iteration's [A] protects Xs
    }

    __syncthreads();
    // ---- write result (B, 97, C) ----
    for (int idx = tid; idx < QP1 * MT; idx += NTHREADS) {
        int q = idx / MT, m = idx - q * MT;
        int row = base + m;
        int b = row >> 4, c = row & 15;
        out[(b * QP1 + q) * CNUM + c] = Xs[aoff(q, m)];
    }
}

extern "C" void kernel_launch(void* const* d_in, const int* in_sizes, int n_in,
                              void* d_out, int out_size)
{
    const float* series     = (const float*)d_in[0];
    const float* rand_error = (const float*)d_in[1];
    const float* W1 = (const float*)d_in[2];
    const float* b1 = (const float*)d_in[3];
    const float* W2 = (const float*)d_in[4];
    const float* b2 = (const float*)d_in[5];
    const float* W3 = (const float*)d_in[6];
    const float* b3 = (const float*)d_in[7];
    float* out = (float*)d_out;

    cudaFuncSetAttribute(arima_flow_kernel,
                         cudaFuncAttributeMaxDynamicSharedMemorySize, SMEM_BYTES);
    arima_flow_kernel<<<ROWS / MT, NTHREADS, SMEM_BYTES>>>(
        series, rand_error, W1, b1, W2, b2, W3, b3, out);
}